// round 2
// baseline (speedup 1.0000x reference)
#include <cuda_runtime.h>
#include <cuda_bf16.h>
#include <cstdint>

// ---------------------------------------------------------------------------
// OutlookAttention: B=1, H=256, W=300, C=384, HEADS=12, D=32, K0=3, K1=300,
// S0=2, S1=300, PAD=1, N=128, SCALE=1/sqrt(32)
// ---------------------------------------------------------------------------

#define Hh   256
#define Ww   300
#define Cc   384
#define HEADS 12
#define Dd   32
#define Nn   128
#define Kidx (3*300*3*12)        // 32400
#define Mpix (Hh*Ww)             // 76800
#define SCALE_F 0.17677669529663689f

// -------------------- scratch (__device__ globals, no allocs) --------------
__device__ float g_pooled[Nn * Cc];                 // 128x384
__device__ float g_poolpart[4][Nn][Cc];
__device__ float g_attn[(size_t)Nn * Kidx];         // 128 x 32400 (logits -> probs)
__device__ float g_vpad[(size_t)258 * 300 * Cc];    // padded v, [r*300+q][c]
__device__ float g_y[HEADS * Nn * 3 * Dd];          // [head][n][k][d]
__device__ float g_outpre[(size_t)Mpix * Cc];       // [p][c]

// -------------------- zero the pad strips of vpad --------------------------
// row 0 (300*384), row 257 (300*384), col 0 (258*384)
__global__ void zero_strips_kernel() {
    int i = blockIdx.x * blockDim.x + threadIdx.x;
    if (i < 115200) {
        g_vpad[i] = 0.f;                                       // row 0
    } else if (i < 230400) {
        g_vpad[(size_t)(257 * 300) * Cc + (i - 115200)] = 0.f; // row 257
    } else {
        int t = i - 230400;
        if (t < 258 * Cc) {
            int r = t / Cc, c = t % Cc;
            g_vpad[(size_t)(r * 300) * Cc + c] = 0.f;          // col 0
        }
    }
}

// -------------------- pooling ----------------------------------------------
// pooled[n][c] = mean over 600 elements (rows 2n,2n+1 x all 300 cols)
__global__ void pool_partial_kernel(const float* __restrict__ x) {
    int n = blockIdx.x, part = blockIdx.y, c = threadIdx.x;
    const float* xr = x + (size_t)(2 * n) * Ww * Cc;
    int o = part * 150;
    float s = 0.f;
    #pragma unroll 4
    for (int i = 0; i < 150; i++) s += xr[(size_t)(o + i) * Cc + c];
    g_poolpart[part][n][c] = s;
}

__global__ void pool_reduce_kernel() {
    int n = blockIdx.x, c = threadIdx.x;
    g_pooled[n * Cc + c] =
        (g_poolpart[0][n][c] + g_poolpart[1][n][c] +
         g_poolpart[2][n][c] + g_poolpart[3][n][c]) * (1.f / 600.f);
}

// -------------------- generic SGEMM: C[M][N] = A[M][K] * B[N][K]^T ---------
// 128x128 tile, BK=8, 256 threads, 8x8 per thread.
// REMAP: write row m of C to vpad pixel ((h+1)*300 + (w+1)), skipping w==299.
template <bool REMAP, bool BIAS>
__global__ __launch_bounds__(256)
void sgemm_kernel(const float* __restrict__ A, const float* __restrict__ B,
                  const float* __restrict__ bias, float* __restrict__ C,
                  int M, int N, int K) {
    __shared__ float As[8][128];
    __shared__ float Bs[8][128];
    int tid = threadIdx.x;
    int bm = blockIdx.y * 128;
    int bn = blockIdx.x * 128;
    int lr = tid >> 1;
    int lc = (tid & 1) << 2;
    const float* Aptr = A + (size_t)(bm + lr) * K + lc;
    const float* Bptr = B + (size_t)(bn + lr) * K + lc;
    bool aval = (bm + lr) < M;
    bool bval = (bn + lr) < N;
    int tx = tid & 15, ty = tid >> 4;

    float acc[8][8];
    #pragma unroll
    for (int i = 0; i < 8; i++)
        #pragma unroll
        for (int j = 0; j < 8; j++) acc[i][j] = 0.f;

    for (int k0 = 0; k0 < K; k0 += 8) {
        float4 av = aval ? *(const float4*)(Aptr + k0) : make_float4(0, 0, 0, 0);
        float4 bv = bval ? *(const float4*)(Bptr + k0) : make_float4(0, 0, 0, 0);
        __syncthreads();
        As[lc + 0][lr] = av.x; As[lc + 1][lr] = av.y;
        As[lc + 2][lr] = av.z; As[lc + 3][lr] = av.w;
        Bs[lc + 0][lr] = bv.x; Bs[lc + 1][lr] = bv.y;
        Bs[lc + 2][lr] = bv.z; Bs[lc + 3][lr] = bv.w;
        __syncthreads();
        #pragma unroll
        for (int kk = 0; kk < 8; kk++) {
            float4 a0 = *(const float4*)&As[kk][ty * 8];
            float4 a1 = *(const float4*)&As[kk][ty * 8 + 4];
            float4 b0 = *(const float4*)&Bs[kk][tx * 8];
            float4 b1 = *(const float4*)&Bs[kk][tx * 8 + 4];
            float af[8] = {a0.x, a0.y, a0.z, a0.w, a1.x, a1.y, a1.z, a1.w};
            float bf[8] = {b0.x, b0.y, b0.z, b0.w, b1.x, b1.y, b1.z, b1.w};
            #pragma unroll
            for (int i = 0; i < 8; i++)
                #pragma unroll
                for (int j = 0; j < 8; j++)
                    acc[i][j] = fmaf(af[i], bf[j], acc[i][j]);
        }
    }

    #pragma unroll
    for (int i = 0; i < 8; i++) {
        int m = bm + ty * 8 + i;
        if (m >= M) continue;
        float* crow;
        if (REMAP) {
            int h = m / 300, w = m % 300;
            if (w == 299) continue;
            crow = C + (size_t)((h + 1) * 300 + (w + 1)) * N;
        } else {
            crow = C + (size_t)m * N;
        }
        #pragma unroll
        for (int j = 0; j < 8; j++) {
            int nn = bn + tx * 8 + j;
            if (nn < N) crow[nn] = acc[i][j] + (BIAS ? bias[nn] : 0.f);
        }
    }
}

// -------------------- softmax over contiguous 900-chunks --------------------
// a layout: [n][kidx], segment s = head*3+k0o, base = n*32400 + s*900
__global__ __launch_bounds__(256)
void softmax_kernel(float* __restrict__ a) {
    int seg = blockIdx.x;
    int n = seg / 36, s = seg % 36;
    float* row = a + (size_t)n * Kidx + s * 900;
    int tid = threadIdx.x;
    int lane = tid & 31, warp = tid >> 5;
    __shared__ float red[8];
    __shared__ float bval;

    float v[4];
    float mx = -1e30f;
    #pragma unroll
    for (int t = 0; t < 4; t++) {
        int i = t * 256 + tid;
        v[t] = (i < 900) ? row[i] * SCALE_F : -1e30f;
        mx = fmaxf(mx, v[t]);
    }
    #pragma unroll
    for (int off = 16; off > 0; off >>= 1)
        mx = fmaxf(mx, __shfl_xor_sync(0xffffffffu, mx, off));
    if (lane == 0) red[warp] = mx;
    __syncthreads();
    if (tid == 0) {
        float m = red[0];
        #pragma unroll
        for (int w = 1; w < 8; w++) m = fmaxf(m, red[w]);
        bval = m;
    }
    __syncthreads();
    mx = bval;

    float sum = 0.f;
    #pragma unroll
    for (int t = 0; t < 4; t++) {
        int i = t * 256 + tid;
        if (i < 900) { v[t] = expf(v[t] - mx); sum += v[t]; }
        else v[t] = 0.f;
    }
    #pragma unroll
    for (int off = 16; off > 0; off >>= 1)
        sum += __shfl_xor_sync(0xffffffffu, sum, off);
    if (lane == 0) red[warp] = sum;
    __syncthreads();
    if (tid == 0) {
        float m = 0.f;
        #pragma unroll
        for (int w = 0; w < 8; w++) m += red[w];
        bval = 1.f / m;
    }
    __syncthreads();
    float inv = bval;
    #pragma unroll
    for (int t = 0; t < 4; t++) {
        int i = t * 256 + tid;
        if (i < 900) row[i] = v[t] * inv;
    }
}

// -------------------- y[head][n][k][d] = sum_m a * v_win -------------------
// v_win[m][d] = vpad[(2n)*300 + m][head*32+d]  (the window is a contiguous
// 900-pixel strip in padded layout: index 600n + m)
__global__ __launch_bounds__(96)
void y_kernel(const float* __restrict__ a, const float* __restrict__ vpad,
              float* __restrict__ y) {
    int head = blockIdx.x, n = blockIdx.y;
    int tid = threadIdx.x;
    int k = tid >> 5, d = tid & 31;
    __shared__ float as_[3 * 900];
    const float* abase = a + (size_t)n * Kidx + head * 3 * 900;
    for (int i = tid; i < 2700; i += 96) as_[i] = abase[i];
    __syncthreads();

    const float* vb = vpad + (size_t)(2 * n) * 300 * Cc + head * Dd + d;
    const float* ak = &as_[k * 900];
    float s0 = 0.f, s1 = 0.f, s2 = 0.f, s3 = 0.f;
    #pragma unroll 1
    for (int m = 0; m < 900; m += 4) {
        s0 = fmaf(ak[m + 0], vb[(size_t)(m + 0) * Cc], s0);
        s1 = fmaf(ak[m + 1], vb[(size_t)(m + 1) * Cc], s1);
        s2 = fmaf(ak[m + 2], vb[(size_t)(m + 2) * Cc], s2);
        s3 = fmaf(ak[m + 3], vb[(size_t)(m + 3) * Cc], s3);
    }
    y[((head * Nn + n) * 3 + k) * Dd + d] = (s0 + s1) + (s2 + s3);
}

// -------------------- gather: reproduce tile/reshape/scatter-add -----------
// out_pre[p][c] = sum over (n,k0) with 2n+k0==h+1 of
//   y[j/28800][n][j%3][(j/3)%32],  j = c*900 + k0*300 + (w+1); zero if w==299
// 96 threads: each handles 4 consecutive channels -> float4 store.
__global__ __launch_bounds__(96)
void gather_kernel(const float* __restrict__ y, float* __restrict__ outpre) {
    int p = blockIdx.x;
    int c0 = threadIdx.x * 4;
    int h = p / 300, w = p % 300;
    float4 acc = make_float4(0.f, 0.f, 0.f, 0.f);
    if (w < 299) {
        int q = w + 1, r = h + 1;
        float* accp = &acc.x;
        #pragma unroll
        for (int k0 = 0; k0 < 3; k0++) {
            int n2 = r - k0;
            if ((n2 & 1) == 0) {
                int n = n2 >> 1;
                if (n >= 0 && n < Nn) {
                    #pragma unroll
                    for (int cc = 0; cc < 4; cc++) {
                        int j = (c0 + cc) * 900 + k0 * 300 + q;
                        int head = j / 28800;
                        int k = j % 3;
                        int d = (j / 3) & 31;
                        accp[cc] += y[((head * Nn + n) * 3 + k) * Dd + d];
                    }
                }
            }
        }
    }
    *(float4*)&outpre[(size_t)p * Cc + c0] = acc;
}

// ---------------------------------------------------------------------------
extern "C" void kernel_launch(void* const* d_in, const int* in_sizes, int n_in,
                              void* d_out, int out_size) {
    const float* x      = (const float*)d_in[0];
    const float* w_v    = (const float*)d_in[1];
    const float* w_attn = (const float*)d_in[2];
    const float* b_attn = (const float*)d_in[3];
    const float* w_proj = (const float*)d_in[4];
    const float* b_proj = (const float*)d_in[5];
    float* out = (float*)d_out;

    float *pooled, *attn, *vpad, *y, *outpre;
    cudaGetSymbolAddress((void**)&pooled, g_pooled);
    cudaGetSymbolAddress((void**)&attn,   g_attn);
    cudaGetSymbolAddress((void**)&vpad,   g_vpad);
    cudaGetSymbolAddress((void**)&y,      g_y);
    cudaGetSymbolAddress((void**)&outpre, g_outpre);

    // 1. zero pad strips of vpad
    zero_strips_kernel<<<(230400 + 258 * Cc + 255) / 256, 256>>>();

    // 2. pooling
    pool_partial_kernel<<<dim3(Nn, 4), Cc>>>(x);
    pool_reduce_kernel<<<Nn, Cc>>>();

    // 3. attention logits: [128 x 32400] = pooled @ w_attn^T + b_attn
    sgemm_kernel<false, true><<<dim3((Kidx + 127) / 128, 1), 256>>>(
        pooled, w_attn, b_attn, attn, Nn, Kidx, Cc);

    // 4. softmax over each 900-chunk
    softmax_kernel<<<Nn * 36, 256>>>(attn);

    // 5. v = x @ w_v^T, written into padded layout
    sgemm_kernel<true, false><<<dim3(3, Mpix / 128), 256>>>(
        x, w_v, nullptr, vpad, Mpix, Cc, Cc);

    // 6. y = a @ v_win
    y_kernel<<<dim3(HEADS, Nn), 96>>>(attn, vpad, y);

    // 7. gather (tile/reshape/scatter-add equivalent)
    gather_kernel<<<Mpix, 96>>>(y, outpre);

    // 8. final projection: out = out_pre @ w_proj^T + b_proj
    sgemm_kernel<false, true><<<dim3(3, Mpix / 128), 256>>>(
        outpre, w_proj, b_proj, out, Mpix, Cc, Cc);
}

// round 7
// speedup vs baseline: 1.8597x; 1.8597x over previous
#include <cuda_runtime.h>
#include <cuda_bf16.h>
#include <cstdint>

// ---------------------------------------------------------------------------
// OutlookAttention: B=1, H=256, W=300, C=384, HEADS=12, D=32, K0=3, K1=300,
// S0=2, S1=300, PAD=1, N=128, SCALE=1/sqrt(32)
// GEMMs via mma.sync bf16 (m16n8k16) with hi/lo split (bf16x3) — sm_100-safe
// (tcgen05 requires sm_100a which this harness does not target).
// ---------------------------------------------------------------------------

#define Hh   256
#define Ww   300
#define Cc   384
#define HEADS 12
#define Dd   32
#define Nn   128
#define Kidx (3*300*3*12)        // 32400
#define Mpix (Hh*Ww)             // 76800
#define SCALE_F 0.17677669529663689f

// -------------------- scratch (__device__ globals, no allocs) --------------
__device__ float g_pooled[Nn * Cc];
__device__ float g_poolpart[4][Nn][Cc];
__device__ float g_attn[(size_t)Nn * Kidx];
__device__ float g_vpad[(size_t)258 * 300 * Cc];
__device__ float g_y[HEADS * Nn * 3 * Dd];
__device__ float g_outpre[(size_t)Mpix * Cc];

// ======================= helpers ===========================================
__device__ __forceinline__ uint32_t smem_u32(const void* p) {
    uint32_t a;
    asm("{ .reg .u64 t; cvta.to.shared.u64 t, %1; cvt.u32.u64 %0, t; }"
        : "=r"(a) : "l"(p));
    return a;
}
__device__ __forceinline__ uint32_t swz(uint32_t off) {
    return off ^ ((off >> 3) & 0x70);
}
__device__ __forceinline__ uint32_t pk2(__nv_bfloat16 a, __nv_bfloat16 b) {
    __nv_bfloat162 t(a, b);
    return *reinterpret_cast<uint32_t*>(&t);
}
__device__ __forceinline__ void split_f4(float4 v, uint2& h, uint2& l) {
    __nv_bfloat16 h0 = __float2bfloat16(v.x);
    __nv_bfloat16 h1 = __float2bfloat16(v.y);
    __nv_bfloat16 h2 = __float2bfloat16(v.z);
    __nv_bfloat16 h3 = __float2bfloat16(v.w);
    __nv_bfloat16 l0 = __float2bfloat16(v.x - __bfloat162float(h0));
    __nv_bfloat16 l1 = __float2bfloat16(v.y - __bfloat162float(h1));
    __nv_bfloat16 l2 = __float2bfloat16(v.z - __bfloat162float(h2));
    __nv_bfloat16 l3 = __float2bfloat16(v.w - __bfloat162float(h3));
    h.x = pk2(h0, h1); h.y = pk2(h2, h3);
    l.x = pk2(l0, l1); l.y = pk2(l2, l3);
}
__device__ __forceinline__ void ldsm_x4(uint32_t* r, uint32_t addr) {
    asm volatile("ldmatrix.sync.aligned.m8n8.x4.shared.b16 {%0,%1,%2,%3}, [%4];"
        : "=r"(r[0]), "=r"(r[1]), "=r"(r[2]), "=r"(r[3]) : "r"(addr));
}
__device__ __forceinline__ void ldsm_x2(uint32_t* r, uint32_t addr) {
    asm volatile("ldmatrix.sync.aligned.m8n8.x2.shared.b16 {%0,%1}, [%2];"
        : "=r"(r[0]), "=r"(r[1]) : "r"(addr));
}
__device__ __forceinline__ void mma16816(float* c, const uint32_t* a, const uint32_t* b) {
    asm volatile(
        "mma.sync.aligned.m16n8k16.row.col.f32.bf16.bf16.f32 "
        "{%0,%1,%2,%3},{%4,%5,%6,%7},{%8,%9},{%0,%1,%2,%3};"
        : "+f"(c[0]), "+f"(c[1]), "+f"(c[2]), "+f"(c[3])
        : "r"(a[0]), "r"(a[1]), "r"(a[2]), "r"(a[3]), "r"(b[0]), "r"(b[1]));
}

// ======================= mma.sync GEMM =====================================
// C[128x128 tile] = A[128 x 384] * B[128 x 384]^T  (bf16x3 split)
// EPI: 0 = C row-major stride Nrows, +bias, col guard n<Nrows (logits)
//      1 = remap rows into padded vpad layout, no bias      (v GEMM)
//      2 = C row-major stride 384, +bias                    (proj)
template <int EPI>
__global__ __launch_bounds__(256)
void gemm_mma(const float* __restrict__ A, const float* __restrict__ B,
              const float* __restrict__ bias, float* __restrict__ C, int Nrows)
{
    extern __shared__ __align__(128) char smem[];
    const uint32_t sb = smem_u32(smem);
    const int tid = threadIdx.x;
    const int wid = tid >> 5, lane = tid & 31;
    const int wr = wid & 3;          // warp M tile: 32 rows
    const int wc = wid >> 2;         // warp N tile: 64 cols
    const int bm = blockIdx.y * 128;
    const int bn = blockIdx.x * 128;

    const uint32_t A_H = 0, A_L = 16384, B_H = 32768, B_L = 49152;

    float c[2][8][4];
    #pragma unroll
    for (int mt = 0; mt < 2; mt++)
        #pragma unroll
        for (int nt = 0; nt < 8; nt++)
            #pragma unroll
            for (int q = 0; q < 4; q++) c[mt][nt][q] = 0.f;

    for (int ch = 0; ch < 6; ch++) {
        const int kc = ch * 64;
        __syncthreads();
        // ---- stage A chunk: 128 rows x 64 cols ----
        #pragma unroll
        for (int it = 0; it < 8; it++) {
            int i = it * 256 + tid;
            int row = i >> 4, c4 = (i & 15) << 2;
            float4 v = *(const float4*)(A + (size_t)(bm + row) * 384 + kc + c4);
            uint2 h, l; split_f4(v, h, l);
            uint32_t off = swz((uint32_t)(row * 128 + c4 * 2));
            *(uint2*)(smem + A_H + off) = h;
            *(uint2*)(smem + A_L + off) = l;
        }
        // ---- stage B chunk: 128 rows x 64 cols ----
        #pragma unroll
        for (int it = 0; it < 8; it++) {
            int i = it * 256 + tid;
            int row = i >> 4, c4 = (i & 15) << 2;
            int gr = bn + row;
            float4 v = make_float4(0.f, 0.f, 0.f, 0.f);
            if (gr < Nrows) v = *(const float4*)(B + (size_t)gr * 384 + kc + c4);
            uint2 h, l; split_f4(v, h, l);
            uint32_t off = swz((uint32_t)(row * 128 + c4 * 2));
            *(uint2*)(smem + B_H + off) = h;
            *(uint2*)(smem + B_L + off) = l;
        }
        __syncthreads();

        // ---- warp MMA over the chunk: 4 k-steps of 16 ----
        #pragma unroll
        for (int ks = 0; ks < 4; ks++) {
            uint32_t ah[2][4], al[2][4];
            #pragma unroll
            for (int mt = 0; mt < 2; mt++) {
                uint32_t aoff = swz((uint32_t)((wr * 32 + mt * 16 + (lane & 15)) * 128
                                   + ks * 32 + (lane >> 4) * 16));
                ldsm_x4(ah[mt], sb + A_H + aoff);
                ldsm_x4(al[mt], sb + A_L + aoff);
            }
            #pragma unroll
            for (int nt = 0; nt < 8; nt++) {
                uint32_t boff = swz((uint32_t)((wc * 64 + nt * 8 + (lane & 7)) * 128
                                   + ks * 32 + ((lane >> 3) & 1) * 16));
                uint32_t bh[2], bl[2];
                ldsm_x2(bh, sb + B_H + boff);
                ldsm_x2(bl, sb + B_L + boff);
                #pragma unroll
                for (int mt = 0; mt < 2; mt++) {
                    mma16816(c[mt][nt], ah[mt], bh);
                    mma16816(c[mt][nt], ah[mt], bl);
                    mma16816(c[mt][nt], al[mt], bh);
                }
            }
        }
    }

    // ---- epilogue: lane owns rows r0, r0+8; cols n, n+1 per ntile ----
    #pragma unroll
    for (int mt = 0; mt < 2; mt++) {
        int r0 = bm + wr * 32 + mt * 16 + (lane >> 2);
        int r1 = r0 + 8;
        float *p0, *p1;
        bool v0 = true, v1 = true;
        if (EPI == 1) {
            int h0 = r0 / 300, w0 = r0 % 300;
            int h1 = r1 / 300, w1 = r1 % 300;
            v0 = (w0 != 299); v1 = (w1 != 299);
            p0 = C + (size_t)((h0 + 1) * 300 + (w0 + 1)) * 384;
            p1 = C + (size_t)((h1 + 1) * 300 + (w1 + 1)) * 384;
        } else {
            int ld = (EPI == 0) ? Nrows : 384;
            p0 = C + (size_t)r0 * ld;
            p1 = C + (size_t)r1 * ld;
        }
        #pragma unroll
        for (int nt = 0; nt < 8; nt++) {
            int n = bn + wc * 64 + nt * 8 + (lane & 3) * 2;
            if (EPI == 0 && n >= Nrows) continue;
            float bx = 0.f, by = 0.f;
            if (EPI != 1) { bx = bias[n]; by = bias[n + 1]; }
            if (v0) { float2 o = make_float2(c[mt][nt][0] + bx, c[mt][nt][1] + by);
                      *(float2*)(p0 + n) = o; }
            if (v1) { float2 o = make_float2(c[mt][nt][2] + bx, c[mt][nt][3] + by);
                      *(float2*)(p1 + n) = o; }
        }
    }
}

// -------------------- zero the pad strips of vpad --------------------------
__global__ void zero_strips_kernel() {
    int i = blockIdx.x * blockDim.x + threadIdx.x;
    if (i < 115200) {
        g_vpad[i] = 0.f;
    } else if (i < 230400) {
        g_vpad[(size_t)(257 * 300) * Cc + (i - 115200)] = 0.f;
    } else {
        int t = i - 230400;
        if (t < 258 * Cc) {
            int r = t / Cc, c = t % Cc;
            g_vpad[(size_t)(r * 300) * Cc + c] = 0.f;
        }
    }
}

// -------------------- pooling ----------------------------------------------
__global__ void pool_partial_kernel(const float* __restrict__ x) {
    int n = blockIdx.x, part = blockIdx.y, c = threadIdx.x;
    const float* xr = x + (size_t)(2 * n) * Ww * Cc;
    int o = part * 150;
    float s = 0.f;
    #pragma unroll 4
    for (int i = 0; i < 150; i++) s += xr[(size_t)(o + i) * Cc + c];
    g_poolpart[part][n][c] = s;
}
__global__ void pool_reduce_kernel() {
    int n = blockIdx.x, c = threadIdx.x;
    g_pooled[n * Cc + c] =
        (g_poolpart[0][n][c] + g_poolpart[1][n][c] +
         g_poolpart[2][n][c] + g_poolpart[3][n][c]) * (1.f / 600.f);
}

// -------------------- softmax over contiguous 900-chunks --------------------
__global__ __launch_bounds__(256)
void softmax_kernel(float* __restrict__ a) {
    int seg = blockIdx.x;
    int n = seg / 36, s = seg % 36;
    float* row = a + (size_t)n * Kidx + s * 900;
    int tid = threadIdx.x;
    int lane = tid & 31, warp = tid >> 5;
    __shared__ float red[8];
    __shared__ float bval;

    float v[4];
    float mx = -1e30f;
    #pragma unroll
    for (int t = 0; t < 4; t++) {
        int i = t * 256 + tid;
        v[t] = (i < 900) ? row[i] * SCALE_F : -1e30f;
        mx = fmaxf(mx, v[t]);
    }
    #pragma unroll
    for (int off = 16; off > 0; off >>= 1)
        mx = fmaxf(mx, __shfl_xor_sync(0xffffffffu, mx, off));
    if (lane == 0) red[warp] = mx;
    __syncthreads();
    if (tid == 0) {
        float m = red[0];
        #pragma unroll
        for (int w = 1; w < 8; w++) m = fmaxf(m, red[w]);
        bval = m;
    }
    __syncthreads();
    mx = bval;

    float sum = 0.f;
    #pragma unroll
    for (int t = 0; t < 4; t++) {
        int i = t * 256 + tid;
        if (i < 900) { v[t] = expf(v[t] - mx); sum += v[t]; }
        else v[t] = 0.f;
    }
    #pragma unroll
    for (int off = 16; off > 0; off >>= 1)
        sum += __shfl_xor_sync(0xffffffffu, sum, off);
    if (lane == 0) red[warp] = sum;
    __syncthreads();
    if (tid == 0) {
        float m = 0.f;
        #pragma unroll
        for (int w = 0; w < 8; w++) m += red[w];
        bval = 1.f / m;
    }
    __syncthreads();
    float inv = bval;
    #pragma unroll
    for (int t = 0; t < 4; t++) {
        int i = t * 256 + tid;
        if (i < 900) row[i] = v[t] * inv;
    }
}

// -------------------- y[head][n][k][d] = sum_m a * v_win -------------------
__global__ __launch_bounds__(96)
void y_kernel(const float* __restrict__ a, const float* __restrict__ vpad,
              float* __restrict__ y) {
    int head = blockIdx.x, n = blockIdx.y;
    int tid = threadIdx.x;
    int k = tid >> 5, d = tid & 31;
    __shared__ float as_[3 * 900];
    const float* abase = a + (size_t)n * Kidx + head * 3 * 900;
    for (int i = tid; i < 2700; i += 96) as_[i] = abase[i];
    __syncthreads();

    const float* vb = vpad + (size_t)(2 * n) * 300 * Cc + head * Dd + d;
    const float* ak = &as_[k * 900];
    float s0 = 0.f, s1 = 0.f, s2 = 0.f, s3 = 0.f;
    #pragma unroll 1
    for (int m = 0; m < 900; m += 4) {
        s0 = fmaf(ak[m + 0], vb[(size_t)(m + 0) * Cc], s0);
        s1 = fmaf(ak[m + 1], vb[(size_t)(m + 1) * Cc], s1);
        s2 = fmaf(ak[m + 2], vb[(size_t)(m + 2) * Cc], s2);
        s3 = fmaf(ak[m + 3], vb[(size_t)(m + 3) * Cc], s3);
    }
    y[((head * Nn + n) * 3 + k) * Dd + d] = (s0 + s1) + (s2 + s3);
}

// -------------------- gather ------------------------------------------------
__global__ __launch_bounds__(96)
void gather_kernel(const float* __restrict__ y, float* __restrict__ outpre) {
    int p = blockIdx.x;
    int c0 = threadIdx.x * 4;
    int h = p / 300, w = p % 300;
    float4 acc = make_float4(0.f, 0.f, 0.f, 0.f);
    if (w < 299) {
        int q = w + 1, r = h + 1;
        float* accp = &acc.x;
        #pragma unroll
        for (int k0 = 0; k0 < 3; k0++) {
            int n2 = r - k0;
            if ((n2 & 1) == 0) {
                int n = n2 >> 1;
                if (n >= 0 && n < Nn) {
                    #pragma unroll
                    for (int cc = 0; cc < 4; cc++) {
                        int j = (c0 + cc) * 900 + k0 * 300 + q;
                        int head = j / 28800;
                        int k = j % 3;
                        int d = (j / 3) & 31;
                        accp[cc] += y[((head * Nn + n) * 3 + k) * Dd + d];
                    }
                }
            }
        }
    }
    *(float4*)&outpre[(size_t)p * Cc + c0] = acc;
}

// ---------------------------------------------------------------------------
extern "C" void kernel_launch(void* const* d_in, const int* in_sizes, int n_in,
                              void* d_out, int out_size) {
    const float* x      = (const float*)d_in[0];
    const float* w_v    = (const float*)d_in[1];
    const float* w_attn = (const float*)d_in[2];
    const float* b_attn = (const float*)d_in[3];
    const float* w_proj = (const float*)d_in[4];
    const float* b_proj = (const float*)d_in[5];
    float* out = (float*)d_out;

    float *pooled, *attn, *vpad, *y, *outpre;
    cudaGetSymbolAddress((void**)&pooled, g_pooled);
    cudaGetSymbolAddress((void**)&attn,   g_attn);
    cudaGetSymbolAddress((void**)&vpad,   g_vpad);
    cudaGetSymbolAddress((void**)&y,      g_y);
    cudaGetSymbolAddress((void**)&outpre, g_outpre);

    const int SMEM = 65536;
    cudaFuncSetAttribute(gemm_mma<0>, cudaFuncAttributeMaxDynamicSharedMemorySize, SMEM);
    cudaFuncSetAttribute(gemm_mma<1>, cudaFuncAttributeMaxDynamicSharedMemorySize, SMEM);
    cudaFuncSetAttribute(gemm_mma<2>, cudaFuncAttributeMaxDynamicSharedMemorySize, SMEM);

    // 1. zero pad strips of vpad
    zero_strips_kernel<<<(230400 + 258 * Cc + 255) / 256, 256>>>();

    // 2. pooling
    pool_partial_kernel<<<dim3(Nn, 4), Cc>>>(x);
    pool_reduce_kernel<<<Nn, Cc>>>();

    // 3. logits: [128 x 32400] = pooled @ w_attn^T + b_attn
    gemm_mma<0><<<dim3(254, 1), 256, SMEM>>>(pooled, w_attn, b_attn, attn, Kidx);

    // 4. softmax over each 900-chunk
    softmax_kernel<<<Nn * 36, 256>>>(attn);

    // 5. v = x @ w_v^T into padded layout
    gemm_mma<1><<<dim3(3, Mpix / 128), 256, SMEM>>>(x, w_v, nullptr, vpad, Cc);

    // 6. y = a @ v_win
    y_kernel<<<dim3(HEADS, Nn), 96>>>(attn, vpad, y);

    // 7. gather
    gather_kernel<<<Mpix, 96>>>(y, outpre);

    // 8. out = out_pre @ w_proj^T + b_proj
    gemm_mma<2><<<dim3(3, Mpix / 128), 256, SMEM>>>(outpre, w_proj, b_proj, out, Cc);
}

// round 10
// speedup vs baseline: 2.3810x; 1.2803x over previous
#include <cuda_runtime.h>
#include <cuda_bf16.h>
#include <cstdint>

// ---------------------------------------------------------------------------
// OutlookAttention: B=1, H=256, W=300, C=384, HEADS=12, D=32, K0=3, K1=300,
// S0=2, S1=300, PAD=1, N=128, SCALE=1/sqrt(32)
// GEMMs via mma.sync bf16 (m16n8k16), bf16x3 hi/lo split, inputs pre-split,
// cp.async double-buffered staging.
// ---------------------------------------------------------------------------

#define Hh   256
#define Ww   300
#define Cc   384
#define HEADS 12
#define Dd   32
#define Nn   128
#define Kidx (3*300*3*12)        // 32400
#define KidxPad 32512            // 254*128 (pad rows; cols >= Kidx never stored)
#define Mpix (Hh*Ww)             // 76800
#define SCALE_F 0.17677669529663689f

// -------------------- scratch (__device__ globals, no allocs) --------------
__device__ float g_attn[(size_t)Nn * Kidx];
__device__ float g_vpad[(size_t)258 * 300 * Cc];
__device__ float g_y[HEADS * Nn * 3 * Dd];
__device__ float g_poolpart[4][Nn][Cc];
__device__ __nv_bfloat16 g_xh[(size_t)Mpix * Cc],  g_xl[(size_t)Mpix * Cc];
__device__ __nv_bfloat16 g_oph[(size_t)Mpix * Cc], g_opl[(size_t)Mpix * Cc];
__device__ __nv_bfloat16 g_wah[(size_t)KidxPad * Cc], g_wal[(size_t)KidxPad * Cc];
__device__ __nv_bfloat16 g_wvh[Cc * Cc], g_wvl[Cc * Cc];
__device__ __nv_bfloat16 g_wph[Cc * Cc], g_wpl[Cc * Cc];
__device__ __nv_bfloat16 g_ph[Nn * Cc], g_pl[Nn * Cc];

// ======================= helpers ===========================================
__device__ __forceinline__ uint32_t smem_u32(const void* p) {
    uint32_t a;
    asm("{ .reg .u64 t; cvta.to.shared.u64 t, %1; cvt.u32.u64 %0, t; }"
        : "=r"(a) : "l"(p));
    return a;
}
__device__ __forceinline__ uint32_t swz(uint32_t off) {
    return off ^ ((off >> 3) & 0x70);
}
__device__ __forceinline__ uint32_t pk2(__nv_bfloat16 a, __nv_bfloat16 b) {
    __nv_bfloat162 t(a, b);
    return *reinterpret_cast<uint32_t*>(&t);
}
__device__ __forceinline__ void split_f4(float4 v, uint2& h, uint2& l) {
    __nv_bfloat16 h0 = __float2bfloat16(v.x);
    __nv_bfloat16 h1 = __float2bfloat16(v.y);
    __nv_bfloat16 h2 = __float2bfloat16(v.z);
    __nv_bfloat16 h3 = __float2bfloat16(v.w);
    __nv_bfloat16 l0 = __float2bfloat16(v.x - __bfloat162float(h0));
    __nv_bfloat16 l1 = __float2bfloat16(v.y - __bfloat162float(h1));
    __nv_bfloat16 l2 = __float2bfloat16(v.z - __bfloat162float(h2));
    __nv_bfloat16 l3 = __float2bfloat16(v.w - __bfloat162float(h3));
    h.x = pk2(h0, h1); h.y = pk2(h2, h3);
    l.x = pk2(l0, l1); l.y = pk2(l2, l3);
}
__device__ __forceinline__ void cp_async16(uint32_t dst, const void* src) {
    asm volatile("cp.async.cg.shared.global [%0], [%1], 16;"
                 :: "r"(dst), "l"(src));
}
__device__ __forceinline__ void ldsm_x4(uint32_t* r, uint32_t addr) {
    asm volatile("ldmatrix.sync.aligned.m8n8.x4.shared.b16 {%0,%1,%2,%3}, [%4];"
        : "=r"(r[0]), "=r"(r[1]), "=r"(r[2]), "=r"(r[3]) : "r"(addr));
}
__device__ __forceinline__ void ldsm_x2(uint32_t* r, uint32_t addr) {
    asm volatile("ldmatrix.sync.aligned.m8n8.x2.shared.b16 {%0,%1}, [%2];"
        : "=r"(r[0]), "=r"(r[1]) : "r"(addr));
}
__device__ __forceinline__ void mma16816(float* c, const uint32_t* a, const uint32_t* b) {
    asm volatile(
        "mma.sync.aligned.m16n8k16.row.col.f32.bf16.bf16.f32 "
        "{%0,%1,%2,%3},{%4,%5,%6,%7},{%8,%9},{%0,%1,%2,%3};"
        : "+f"(c[0]), "+f"(c[1]), "+f"(c[2]), "+f"(c[3])
        : "r"(a[0]), "r"(a[1]), "r"(a[2]), "r"(a[3]), "r"(b[0]), "r"(b[1]));
}

// -------------------- fp32 -> bf16 hi/lo split pass ------------------------
__global__ __launch_bounds__(256)
void conv_split_kernel(const float* __restrict__ src,
                       __nv_bfloat16* __restrict__ h,
                       __nv_bfloat16* __restrict__ l, int n4) {
    int i = blockIdx.x * blockDim.x + threadIdx.x;
    if (i < n4) {
        float4 v = ((const float4*)src)[i];
        uint2 hh, ll; split_f4(v, hh, ll);
        ((uint2*)h)[i] = hh;
        ((uint2*)l)[i] = ll;
    }
}

// ======================= mma.sync GEMM, cp.async 2-stage ===================
// C[128x128 tile] = A[. x 384] * B[. x 384]^T, A/B pre-split bf16 hi/lo.
// EPI: 0 = C row-major stride Nrows, +bias, col guard n<Nrows (logits)
//      1 = remap rows into padded vpad layout, no bias      (v GEMM)
//      2 = C row-major stride 384, +bias                    (proj)
template <int EPI>
__global__ __launch_bounds__(256)
void gemm_mma(const __nv_bfloat16* __restrict__ Ah, const __nv_bfloat16* __restrict__ Al,
              const __nv_bfloat16* __restrict__ Bh, const __nv_bfloat16* __restrict__ Bl,
              const float* __restrict__ bias, float* __restrict__ C, int Nrows)
{
    extern __shared__ __align__(128) char smem[];
    const uint32_t sb = smem_u32(smem);
    const int tid = threadIdx.x;
    const int wid = tid >> 5, lane = tid & 31;
    const int wr = wid & 3;          // warp M tile: 32 rows
    const int wc = wid >> 2;         // warp N tile: 64 cols
    const int bm = blockIdx.y * 128;
    const int bn = blockIdx.x * 128;
    // stage s at s*65536: A_H +0, A_L +16384, B_H +32768, B_L +49152

    float c[2][8][4];
    #pragma unroll
    for (int mt = 0; mt < 2; mt++)
        #pragma unroll
        for (int nt = 0; nt < 8; nt++)
            #pragma unroll
            for (int q = 0; q < 4; q++) c[mt][nt][q] = 0.f;

    const char* pAh = (const char*)Ah;
    const char* pAl = (const char*)Al;
    const char* pBh = (const char*)Bh;
    const char* pBl = (const char*)Bl;

    auto issue = [&](int ch, int st) {
        uint32_t sbase = sb + st * 65536;
        size_t kb = (size_t)ch * 128;     // 64 bf16 = 128 bytes along K
        #pragma unroll
        for (int it = 0; it < 4; it++) {
            int i = it * 256 + tid;
            int row = i >> 3;
            int c16 = (i & 7) * 16;
            uint32_t doff = swz((uint32_t)(row * 128 + c16));
            size_t aoff = (size_t)(bm + row) * 768 + kb + c16;
            size_t boff = (size_t)(bn + row) * 768 + kb + c16;
            cp_async16(sbase +     0 + doff, pAh + aoff);
            cp_async16(sbase + 16384 + doff, pAl + aoff);
            cp_async16(sbase + 32768 + doff, pBh + boff);
            cp_async16(sbase + 49152 + doff, pBl + boff);
        }
        asm volatile("cp.async.commit_group;");
    };

    issue(0, 0);
    for (int ch = 0; ch < 6; ch++) {
        if (ch > 0) __syncthreads();          // mma(ch-1) done before reuse of its buffer
        if (ch + 1 < 6) {
            issue(ch + 1, (ch + 1) & 1);
            asm volatile("cp.async.wait_group 1;");
        } else {
            asm volatile("cp.async.wait_group 0;");
        }
        __syncthreads();

        const uint32_t A_H = sb + (ch & 1) * 65536;
        const uint32_t A_L = A_H + 16384;
        const uint32_t B_H = A_H + 32768;
        const uint32_t B_L = A_H + 49152;

        #pragma unroll
        for (int ks = 0; ks < 4; ks++) {
            uint32_t ah[2][4], al[2][4];
            #pragma unroll
            for (int mt = 0; mt < 2; mt++) {
                uint32_t aoff = swz((uint32_t)((wr * 32 + mt * 16 + (lane & 15)) * 128
                                   + ks * 32 + (lane >> 4) * 16));
                ldsm_x4(ah[mt], A_H + aoff);
                ldsm_x4(al[mt], A_L + aoff);
            }
            #pragma unroll
            for (int nt = 0; nt < 8; nt++) {
                uint32_t boff = swz((uint32_t)((wc * 64 + nt * 8 + (lane & 7)) * 128
                                   + ks * 32 + ((lane >> 3) & 1) * 16));
                uint32_t bh[2], bl[2];
                ldsm_x2(bh, B_H + boff);
                ldsm_x2(bl, B_L + boff);
                #pragma unroll
                for (int mt = 0; mt < 2; mt++) {
                    mma16816(c[mt][nt], ah[mt], bh);
                    mma16816(c[mt][nt], ah[mt], bl);
                    mma16816(c[mt][nt], al[mt], bh);
                }
            }
        }
    }

    // ---- epilogue ----
    #pragma unroll
    for (int mt = 0; mt < 2; mt++) {
        int r0 = bm + wr * 32 + mt * 16 + (lane >> 2);
        int r1 = r0 + 8;
        float *p0, *p1;
        bool v0 = true, v1 = true;
        if (EPI == 1) {
            int h0 = r0 / 300, w0 = r0 % 300;
            int h1 = r1 / 300, w1 = r1 % 300;
            v0 = (w0 != 299); v1 = (w1 != 299);
            p0 = C + (size_t)((h0 + 1) * 300 + (w0 + 1)) * 384;
            p1 = C + (size_t)((h1 + 1) * 300 + (w1 + 1)) * 384;
        } else {
            int ld = (EPI == 0) ? Nrows : 384;
            p0 = C + (size_t)r0 * ld;
            p1 = C + (size_t)r1 * ld;
        }
        #pragma unroll
        for (int nt = 0; nt < 8; nt++) {
            int n = bn + wc * 64 + nt * 8 + (lane & 3) * 2;
            if (EPI == 0 && n >= Nrows) continue;
            float bx = 0.f, by = 0.f;
            if (EPI != 1) { bx = bias[n]; by = bias[n + 1]; }
            if (v0) { float2 o = make_float2(c[mt][nt][0] + bx, c[mt][nt][1] + by);
                      *(float2*)(p0 + n) = o; }
            if (v1) { float2 o = make_float2(c[mt][nt][2] + bx, c[mt][nt][3] + by);
                      *(float2*)(p1 + n) = o; }
        }
    }
}

// -------------------- zero the pad strips of vpad --------------------------
__global__ void zero_strips_kernel() {
    int i = blockIdx.x * blockDim.x + threadIdx.x;
    if (i < 115200) {
        g_vpad[i] = 0.f;
    } else if (i < 230400) {
        g_vpad[(size_t)(257 * 300) * Cc + (i - 115200)] = 0.f;
    } else {
        int t = i - 230400;
        if (t < 258 * Cc) {
            int r = t / Cc, c = t % Cc;
            g_vpad[(size_t)(r * 300) * Cc + c] = 0.f;
        }
    }
}

// -------------------- pooling ----------------------------------------------
__global__ void pool_partial_kernel(const float* __restrict__ x) {
    int n = blockIdx.x, part = blockIdx.y, c = threadIdx.x;
    const float* xr = x + (size_t)(2 * n) * Ww * Cc;
    int o = part * 150;
    float s = 0.f;
    #pragma unroll 4
    for (int i = 0; i < 150; i++) s += xr[(size_t)(o + i) * Cc + c];
    g_poolpart[part][n][c] = s;
}
__global__ void pool_reduce_kernel() {
    int n = blockIdx.x, c = threadIdx.x;
    float v = (g_poolpart[0][n][c] + g_poolpart[1][n][c] +
               g_poolpart[2][n][c] + g_poolpart[3][n][c]) * (1.f / 600.f);
    __nv_bfloat16 h = __float2bfloat16(v);
    __nv_bfloat16 l = __float2bfloat16(v - __bfloat162float(h));
    g_ph[n * Cc + c] = h;
    g_pl[n * Cc + c] = l;
}

// -------------------- softmax over contiguous 900-chunks --------------------
__global__ __launch_bounds__(256)
void softmax_kernel(float* __restrict__ a) {
    int seg = blockIdx.x;
    int n = seg / 36, s = seg % 36;
    float* row = a + (size_t)n * Kidx + s * 900;
    int tid = threadIdx.x;
    int lane = tid & 31, warp = tid >> 5;
    __shared__ float red[8];
    __shared__ float bval;

    float v[4];
    float mx = -1e30f;
    #pragma unroll
    for (int t = 0; t < 4; t++) {
        int i = t * 256 + tid;
        v[t] = (i < 900) ? row[i] * SCALE_F : -1e30f;
        mx = fmaxf(mx, v[t]);
    }
    #pragma unroll
    for (int off = 16; off > 0; off >>= 1)
        mx = fmaxf(mx, __shfl_xor_sync(0xffffffffu, mx, off));
    if (lane == 0) red[warp] = mx;
    __syncthreads();
    if (tid == 0) {
        float m = red[0];
        #pragma unroll
        for (int w = 1; w < 8; w++) m = fmaxf(m, red[w]);
        bval = m;
    }
    __syncthreads();
    mx = bval;

    float sum = 0.f;
    #pragma unroll
    for (int t = 0; t < 4; t++) {
        int i = t * 256 + tid;
        if (i < 900) { v[t] = expf(v[t] - mx); sum += v[t]; }
        else v[t] = 0.f;
    }
    #pragma unroll
    for (int off = 16; off > 0; off >>= 1)
        sum += __shfl_xor_sync(0xffffffffu, sum, off);
    if (lane == 0) red[warp] = sum;
    __syncthreads();
    if (tid == 0) {
        float m = 0.f;
        #pragma unroll
        for (int w = 0; w < 8; w++) m += red[w];
        bval = 1.f / m;
    }
    __syncthreads();
    float inv = bval;
    #pragma unroll
    for (int t = 0; t < 4; t++) {
        int i = t * 256 + tid;
        if (i < 900) row[i] = v[t] * inv;
    }
}

// -------------------- y[head][n][k][d] = sum_m a * v_win -------------------
__global__ __launch_bounds__(96)
void y_kernel(const float* __restrict__ a, const float* __restrict__ vpad,
              float* __restrict__ y) {
    int head = blockIdx.x, n = blockIdx.y;
    int tid = threadIdx.x;
    int k = tid >> 5, d = tid & 31;
    __shared__ float as_[3 * 900];
    const float* abase = a + (size_t)n * Kidx + head * 3 * 900;
    for (int i = tid; i < 2700; i += 96) as_[i] = abase[i];
    __syncthreads();

    const float* vb = vpad + (size_t)(2 * n) * 300 * Cc + head * Dd + d;
    const float* ak = &as_[k * 900];
    float s0 = 0.f, s1 = 0.f, s2 = 0.f, s3 = 0.f;
    #pragma unroll 1
    for (int m = 0; m < 900; m += 4) {
        s0 = fmaf(ak[m + 0], vb[(size_t)(m + 0) * Cc], s0);
        s1 = fmaf(ak[m + 1], vb[(size_t)(m + 1) * Cc], s1);
        s2 = fmaf(ak[m + 2], vb[(size_t)(m + 2) * Cc], s2);
        s3 = fmaf(ak[m + 3], vb[(size_t)(m + 3) * Cc], s3);
    }
    y[((head * Nn + n) * 3 + k) * Dd + d] = (s0 + s1) + (s2 + s3);
}

// -------------------- gather: writes bf16 hi/lo outpre ----------------------
__global__ __launch_bounds__(96)
void gather_kernel(const float* __restrict__ y) {
    int p = blockIdx.x;
    int c0 = threadIdx.x * 4;
    int h = p / 300, w = p % 300;
    float4 acc = make_float4(0.f, 0.f, 0.f, 0.f);
    if (w < 299) {
        int q = w + 1, r = h + 1;
        float* accp = &acc.x;
        #pragma unroll
        for (int k0 = 0; k0 < 3; k0++) {
            int n2 = r - k0;
            if ((n2 & 1) == 0) {
                int n = n2 >> 1;
                if (n >= 0 && n < Nn) {
                    #pragma unroll
                    for (int cc = 0; cc < 4; cc++) {
                        int j = (c0 + cc) * 900 + k0 * 300 + q;
                        int head = j / 28800;
                        int k = j % 3;
                        int d = (j / 3) & 31;
                        accp[cc] += y[((head * Nn + n) * 3 + k) * Dd + d];
                    }
                }
            }
        }
    }
    uint2 hh, ll; split_f4(acc, hh, ll);
    ((uint2*)(g_oph + (size_t)p * Cc))[threadIdx.x] = hh;
    ((uint2*)(g_opl + (size_t)p * Cc))[threadIdx.x] = ll;
}

// ---------------------------------------------------------------------------
extern "C" void kernel_launch(void* const* d_in, const int* in_sizes, int n_in,
                              void* d_out, int out_size) {
    const float* x      = (const float*)d_in[0];
    const float* w_v    = (const float*)d_in[1];
    const float* w_attn = (const float*)d_in[2];
    const float* b_attn = (const float*)d_in[3];
    const float* w_proj = (const float*)d_in[4];
    const float* b_proj = (const float*)d_in[5];
    float* out = (float*)d_out;

    float *attn, *vpad, *y;
    __nv_bfloat16 *xh, *xl, *oph, *opl, *wah, *wal, *wvh, *wvl, *wph, *wpl, *ph, *pl;
    cudaGetSymbolAddress((void**)&attn, g_attn);
    cudaGetSymbolAddress((void**)&vpad, g_vpad);
    cudaGetSymbolAddress((void**)&y,    g_y);
    cudaGetSymbolAddress((void**)&xh,  g_xh);   cudaGetSymbolAddress((void**)&xl,  g_xl);
    cudaGetSymbolAddress((void**)&oph, g_oph);  cudaGetSymbolAddress((void**)&opl, g_opl);
    cudaGetSymbolAddress((void**)&wah, g_wah);  cudaGetSymbolAddress((void**)&wal, g_wal);
    cudaGetSymbolAddress((void**)&wvh, g_wvh);  cudaGetSymbolAddress((void**)&wvl, g_wvl);
    cudaGetSymbolAddress((void**)&wph, g_wph);  cudaGetSymbolAddress((void**)&wpl, g_wpl);
    cudaGetSymbolAddress((void**)&ph,  g_ph);   cudaGetSymbolAddress((void**)&pl,  g_pl);

    const int SMEM = 131072;   // 2 stages x 4 tiles x 16KB
    cudaFuncSetAttribute(gemm_mma<0>, cudaFuncAttributeMaxDynamicSharedMemorySize, SMEM);
    cudaFuncSetAttribute(gemm_mma<1>, cudaFuncAttributeMaxDynamicSharedMemorySize, SMEM);
    cudaFuncSetAttribute(gemm_mma<2>, cudaFuncAttributeMaxDynamicSharedMemorySize, SMEM);

    // 0. pre-split inputs to bf16 hi/lo
    conv_split_kernel<<<(Mpix * Cc / 4 + 255) / 256, 256>>>(x, xh, xl, Mpix * Cc / 4);
    conv_split_kernel<<<(Cc * Cc / 4 + 255) / 256, 256>>>(w_v, wvh, wvl, Cc * Cc / 4);
    conv_split_kernel<<<(Kidx * Cc / 4 + 255) / 256, 256>>>(w_attn, wah, wal, Kidx * Cc / 4);
    conv_split_kernel<<<(Cc * Cc / 4 + 255) / 256, 256>>>(w_proj, wph, wpl, Cc * Cc / 4);

    // 1. zero pad strips of vpad
    zero_strips_kernel<<<(230400 + 258 * Cc + 255) / 256, 256>>>();

    // 2. pooling (emits bf16 hi/lo pooled)
    pool_partial_kernel<<<dim3(Nn, 4), Cc>>>(x);
    pool_reduce_kernel<<<Nn, Cc>>>();

    // 3. logits: [128 x 32400] = pooled @ w_attn^T + b_attn
    gemm_mma<0><<<dim3(254, 1), 256, SMEM>>>(ph, pl, wah, wal, b_attn, attn, Kidx);

    // 4. softmax over each 900-chunk
    softmax_kernel<<<Nn * 36, 256>>>(attn);

    // 5. v = x @ w_v^T into padded layout
    gemm_mma<1><<<dim3(3, Mpix / 128), 256, SMEM>>>(xh, xl, wvh, wvl, nullptr, vpad, Cc);

    // 6. y = a @ v_win
    y_kernel<<<dim3(HEADS, Nn), 96>>>(attn, vpad, y);

    // 7. gather (emits bf16 hi/lo outpre)
    gather_kernel<<<Mpix, 96>>>(y);

    // 8. out = out_pre @ w_proj^T + b_proj
    gemm_mma<2><<<dim3(3, Mpix / 128), 256, SMEM>>>(oph, opl, wph, wpl, b_proj, out, Cc);
}